// round 2
// baseline (speedup 1.0000x reference)
#include <cuda_runtime.h>
#include <math.h>

#define RT   128   // tokens per block tile
#define NE   64    // experts (E)
#define KC   32    // K-chunk
#define KMAX 8     // max supported top_k

// GEMM (fp32, register-tiled) + fused softmax + top-k epilogue.
// x: [N, D] row-major, w: [E=64, D] row-major (both K-contiguous).
// out layout: [N*k] topk_probs | [N*k] topk_indices(as float) | [N*64] probs
__global__ __launch_bounds__(256, 2) void router_kernel(
    const float* __restrict__ x,
    const float* __restrict__ w,
    const int*   __restrict__ topk_ptr,
    float* __restrict__ out,
    int N, int D)
{
    // smem: GEMM buffers overlap with logits buffer (reused after mainloop)
    // As: [RT][KC+1] = 128*33, Ws: [NE][KC+1] = 64*33  -> 6336 floats
    // L : [RT][NE+1] = 128*65                          -> 8320 floats
    __shared__ float smem_buf[RT * (NE + 1)];
    float* As = smem_buf;                 // [RT][33]
    float* Ws = smem_buf + RT * (KC + 1); // [64][33]
    float* L  = smem_buf;                 // [RT][65] (aliases As/Ws after sync)

    const int tid = threadIdx.x;
    const int tx  = tid & 15;   // expert group
    const int ty  = tid >> 4;   // token group
    const int t0  = blockIdx.x * RT;

    float acc[8][4];
#pragma unroll
    for (int i = 0; i < 8; i++)
#pragma unroll
        for (int j = 0; j < 4; j++) acc[i][j] = 0.f;

    for (int k0 = 0; k0 < D; k0 += KC) {
        // Load A tile: 128 rows x 32 cols = 1024 float4; 4 per thread, coalesced.
#pragma unroll
        for (int q = 0; q < 4; q++) {
            int id = tid + q * 256;            // 0..1023
            int r  = id >> 3;                  // row (8 float4 per row)
            int c  = (id & 7) << 2;            // col
            float4 v = *(const float4*)(x + (size_t)(t0 + r) * D + k0 + c);
            As[r * (KC + 1) + c + 0] = v.x;
            As[r * (KC + 1) + c + 1] = v.y;
            As[r * (KC + 1) + c + 2] = v.z;
            As[r * (KC + 1) + c + 3] = v.w;
        }
        // Load W tile: 64 rows x 32 cols = 512 float4; 2 per thread.
#pragma unroll
        for (int q = 0; q < 2; q++) {
            int id = tid + q * 256;            // 0..511
            int r  = id >> 3;
            int c  = (id & 7) << 2;
            float4 v = *(const float4*)(w + (size_t)r * D + k0 + c);
            Ws[r * (KC + 1) + c + 0] = v.x;
            Ws[r * (KC + 1) + c + 1] = v.y;
            Ws[r * (KC + 1) + c + 2] = v.z;
            Ws[r * (KC + 1) + c + 3] = v.w;
        }
        __syncthreads();

#pragma unroll
        for (int kk = 0; kk < KC; kk++) {
            float a[8], b[4];
#pragma unroll
            for (int i = 0; i < 8; i++) a[i] = As[(ty + 16 * i) * (KC + 1) + kk];
#pragma unroll
            for (int j = 0; j < 4; j++) b[j] = Ws[(tx + 16 * j) * (KC + 1) + kk];
#pragma unroll
            for (int i = 0; i < 8; i++)
#pragma unroll
                for (int j = 0; j < 4; j++)
                    acc[i][j] = fmaf(a[i], b[j], acc[i][j]);
        }
        __syncthreads();
    }

    // Dump logits to smem (overwrites As/Ws)
#pragma unroll
    for (int i = 0; i < 8; i++)
#pragma unroll
        for (int j = 0; j < 4; j++)
            L[(ty + 16 * i) * (NE + 1) + (tx + 16 * j)] = acc[i][j];
    __syncthreads();

    // ---- Epilogue: softmax over 64 experts + top-k per row ----
    const int warp = tid >> 5;
    const int lane = tid & 31;
    int k = *topk_ptr;                    // uniform device-side read
    if (k < 1) k = 1;
    if (k > KMAX) k = KMAX;

    float* out_tp = out;                          // [N, k] topk probs
    float* out_ti = out + (size_t)N * k;          // [N, k] topk indices (float)
    float* out_pr = out + (size_t)2 * N * k;      // [N, 64] probs

    for (int rr = warp; rr < RT; rr += 8) {
        const int row = t0 + rr;
        const float* Lr = L + rr * (NE + 1);
        float p0 = Lr[lane];
        float p1 = Lr[lane + 32];

        // warp max
        float m = fmaxf(p0, p1);
#pragma unroll
        for (int o = 16; o > 0; o >>= 1) m = fmaxf(m, __shfl_xor_sync(~0u, m, o));

        float e0 = expf(p0 - m), e1 = expf(p1 - m);
        float s = e0 + e1;
#pragma unroll
        for (int o = 16; o > 0; o >>= 1) s += __shfl_xor_sync(~0u, s, o);
        const float inv = 1.0f / s;
        const float v0 = e0 * inv, v1 = e1 * inv;

        out_pr[(size_t)row * NE + lane]      = v0;
        out_pr[(size_t)row * NE + lane + 32] = v1;

        // iterative top-k (argmax with lowest-index tie-break, like lax.top_k)
        float c0 = v0, c1 = v1;
        float ts = 0.f;
        float myv = 0.f; int myi = 0;
#pragma unroll
        for (int t = 0; t < KMAX; t++) {
            if (t >= k) break;
            float bv; int bi;
            if (c0 >= c1) { bv = c0; bi = lane; }       // lane < lane+32: tie -> lower idx
            else          { bv = c1; bi = lane + 32; }
#pragma unroll
            for (int o = 16; o > 0; o >>= 1) {
                float ov = __shfl_xor_sync(~0u, bv, o);
                int   oi = __shfl_xor_sync(~0u, bi, o);
                if (ov > bv || (ov == bv && oi < bi)) { bv = ov; bi = oi; }
            }
            ts += bv;
            if (lane == t) { myv = bv; myi = bi; }
            if (bi == lane)      c0 = -1.f;
            if (bi == lane + 32) c1 = -1.f;
        }
        if (lane < k) {
            const float tinv = 1.0f / ts;
            out_tp[(size_t)row * k + lane] = myv * tinv;
            out_ti[(size_t)row * k + lane] = (float)myi;
        }
    }
}

extern "C" void kernel_launch(void* const* d_in, const int* in_sizes, int n_in,
                              void* d_out, int out_size) {
    const float* x    = (const float*)d_in[0];
    const float* w    = (const float*)d_in[1];
    const int*   topk = (const int*)d_in[2];
    float* out = (float*)d_out;

    const double s0 = (double)in_sizes[0];   // N*D
    const double s1 = (double)in_sizes[1];   // E*D
    // out_size = N*(2k + E), E = s1*N/s0  ->  (s1/s0)*N^2 + 2k*N - out_size = 0
    // k is a device scalar; assume k=2 for shape solving (holds for this dataset).
    const int kk = 2;
    const double r = s1 / s0;
    double Nd = (-2.0 * kk + sqrt(4.0 * kk * kk + 4.0 * r * (double)out_size)) / (2.0 * r);
    int N = (int)(Nd + 0.5);
    if (N <= 0) N = 16384;
    int D = (int)(s0 / N + 0.5);

    int grid = (N + RT - 1) / RT;
    router_kernel<<<grid, 256>>>(x, w, topk, out, N, D);
}

// round 5
// speedup vs baseline: 3.2399x; 3.2399x over previous
#include <cuda_runtime.h>
#include <cuda_bf16.h>
#include <cstdint>
#include <math.h>

#define NE    64     // experts
#define MT    128    // tokens per CTA
#define KB    64     // K per chunk (64 bf16 = 128B row, SW128 atom)
#define KMAX  8

// smem byte offsets (single-buffered; logits L aliases everything afterwards)
#define OFF_AH 0          // [128][128B] bf16 hi
#define OFF_AL 16384      // [128][128B] bf16 lo
#define OFF_BH 32768      // [64][128B]
#define OFF_BL 40960      // [64][128B]
#define SMEM_TOTAL 49152

__device__ __forceinline__ uint32_t sw128(uint32_t off) {
    return off ^ ((off >> 3) & 0x70);
}

// fp32 pair -> bf16x2 hi + bf16x2 lo residual
__device__ __forceinline__ void cvt_hilo(float x, float y, uint32_t& h, uint32_t& l) {
    asm("cvt.rn.bf16x2.f32 %0, %1, %2;" : "=r"(h) : "f"(y), "f"(x));
    float hx = __uint_as_float(h << 16);
    float hy = __uint_as_float(h & 0xffff0000u);
    float lx = x - hx, ly = y - hy;
    asm("cvt.rn.bf16x2.f32 %0, %1, %2;" : "=r"(l) : "f"(ly), "f"(lx));
}

__device__ __forceinline__ void mma_bf16(float* c, const uint32_t* a, const uint32_t* b) {
    asm volatile(
        "mma.sync.aligned.m16n8k16.row.col.f32.bf16.bf16.f32 "
        "{%0,%1,%2,%3}, {%4,%5,%6,%7}, {%8,%9}, {%0,%1,%2,%3};"
        : "+f"(c[0]), "+f"(c[1]), "+f"(c[2]), "+f"(c[3])
        : "r"(a[0]), "r"(a[1]), "r"(a[2]), "r"(a[3]), "r"(b[0]), "r"(b[1]));
}

extern __shared__ __align__(1024) unsigned char smem[];

__global__ __launch_bounds__(256, 1)
void router_mma_kernel(const float* __restrict__ x,
                       const float* __restrict__ w,
                       const int*   __restrict__ topk_ptr,
                       float* __restrict__ out,
                       int N, int D)
{
    const int tid  = threadIdx.x;
    const int wid  = tid >> 5;
    const int lane = tid & 31;
    const int t0   = blockIdx.x * MT;

    // 8 warps: 4 m-groups x 2 n-groups; each warp computes 32 rows x 32 cols
    const int Rb = (wid >> 1) * 32;      // warp row base within tile
    const int Cb = (wid & 1) * 32;       // warp col base

    const int l4  = lane >> 2;           // 0..7
    const int lkp = lane & 3;            // 0..3

    float acc[2][4][4];
#pragma unroll
    for (int mt = 0; mt < 2; mt++)
#pragma unroll
        for (int nt = 0; nt < 4; nt++)
#pragma unroll
            for (int i = 0; i < 4; i++) acc[mt][nt][i] = 0.f;

    float4 Areg[8], Breg[4];
    const int NC = D / KB;               // 32 chunks

    // ---- prologue: prefetch chunk 0 ----
    {
        const int k0 = 0;
#pragma unroll
        for (int q = 0; q < 8; q++) {
            int id = tid + q * 256, r = id >> 4, c4 = id & 15;
            Areg[q] = *(const float4*)(x + (size_t)(t0 + r) * D + k0 + c4 * 4);
        }
#pragma unroll
        for (int q = 0; q < 4; q++) {
            int id = tid + q * 256, r = id >> 4, c4 = id & 15;
            Breg[q] = *(const float4*)(w + (size_t)r * D + k0 + c4 * 4);
        }
    }

    for (int kc = 0; kc < NC; kc++) {
        if (kc) __syncthreads();         // prev compute done before overwriting smem

        // ---- convert + store tiles (hi/lo bf16, SW128) ----
#pragma unroll
        for (int q = 0; q < 8; q++) {
            int id = tid + q * 256, r = id >> 4, c4 = id & 15;
            uint32_t h0, l0, h1, l1;
            cvt_hilo(Areg[q].x, Areg[q].y, h0, l0);
            cvt_hilo(Areg[q].z, Areg[q].w, h1, l1);
            uint32_t sw = sw128((uint32_t)(r * 128 + c4 * 8));
            *(uint2*)(smem + OFF_AH + sw) = make_uint2(h0, h1);
            *(uint2*)(smem + OFF_AL + sw) = make_uint2(l0, l1);
        }
#pragma unroll
        for (int q = 0; q < 4; q++) {
            int id = tid + q * 256, r = id >> 4, c4 = id & 15;
            uint32_t h0, l0, h1, l1;
            cvt_hilo(Breg[q].x, Breg[q].y, h0, l0);
            cvt_hilo(Breg[q].z, Breg[q].w, h1, l1);
            uint32_t sw = sw128((uint32_t)(r * 128 + c4 * 8));
            *(uint2*)(smem + OFF_BH + sw) = make_uint2(h0, h1);
            *(uint2*)(smem + OFF_BL + sw) = make_uint2(l0, l1);
        }
        __syncthreads();

        // ---- prefetch next chunk (LDG overlaps compute below) ----
        if (kc + 1 < NC) {
            const int k0 = (kc + 1) * KB;
#pragma unroll
            for (int q = 0; q < 8; q++) {
                int id = tid + q * 256, r = id >> 4, c4 = id & 15;
                Areg[q] = *(const float4*)(x + (size_t)(t0 + r) * D + k0 + c4 * 4);
            }
#pragma unroll
            for (int q = 0; q < 4; q++) {
                int id = tid + q * 256, r = id >> 4, c4 = id & 15;
                Breg[q] = *(const float4*)(w + (size_t)r * D + k0 + c4 * 4);
            }
        }

        // ---- compute: 4 k16 steps ----
#pragma unroll
        for (int ks = 0; ks < 4; ks++) {
            // B fragments: 4 n-tiles, hi + lo (shared across both m-tiles)
            uint32_t bh[4][2], bl[4][2];
#pragma unroll
            for (int nt = 0; nt < 4; nt++) {
                uint32_t b0 = (uint32_t)((Cb + nt * 8 + l4) * 128 + ks * 32 + lkp * 4);
                bh[nt][0] = *(const uint32_t*)(smem + OFF_BH + sw128(b0));
                bh[nt][1] = *(const uint32_t*)(smem + OFF_BH + sw128(b0 + 16));
                bl[nt][0] = *(const uint32_t*)(smem + OFF_BL + sw128(b0));
                bl[nt][1] = *(const uint32_t*)(smem + OFF_BL + sw128(b0 + 16));
            }
#pragma unroll
            for (int mt = 0; mt < 2; mt++) {
                uint32_t a0 = (uint32_t)((Rb + mt * 16 + l4) * 128 + ks * 32 + lkp * 4);
                uint32_t a1 = a0 + 8 * 128;
                uint32_t ah[4], al[4];
                ah[0] = *(const uint32_t*)(smem + OFF_AH + sw128(a0));
                ah[1] = *(const uint32_t*)(smem + OFF_AH + sw128(a1));
                ah[2] = *(const uint32_t*)(smem + OFF_AH + sw128(a0 + 16));
                ah[3] = *(const uint32_t*)(smem + OFF_AH + sw128(a1 + 16));
                al[0] = *(const uint32_t*)(smem + OFF_AL + sw128(a0));
                al[1] = *(const uint32_t*)(smem + OFF_AL + sw128(a1));
                al[2] = *(const uint32_t*)(smem + OFF_AL + sw128(a0 + 16));
                al[3] = *(const uint32_t*)(smem + OFF_AL + sw128(a1 + 16));
#pragma unroll
                for (int nt = 0; nt < 4; nt++) {
                    mma_bf16(acc[mt][nt], ah, bh[nt]);
                    mma_bf16(acc[mt][nt], ah, bl[nt]);
                    mma_bf16(acc[mt][nt], al, bh[nt]);
                }
            }
        }
    }

    // ---- dump logits to smem L[128][65] (aliases A/B tiles) ----
    __syncthreads();
    float* L = (float*)smem;
#pragma unroll
    for (int mt = 0; mt < 2; mt++)
#pragma unroll
        for (int nt = 0; nt < 4; nt++) {
            int r0 = Rb + mt * 16 + l4;
            int c0 = Cb + nt * 8 + lkp * 2;
            L[r0 * 65 + c0]           = acc[mt][nt][0];
            L[r0 * 65 + c0 + 1]       = acc[mt][nt][1];
            L[(r0 + 8) * 65 + c0]     = acc[mt][nt][2];
            L[(r0 + 8) * 65 + c0 + 1] = acc[mt][nt][3];
        }
    __syncthreads();

    // ---- epilogue: one thread per row, thread-local softmax + top-k ----
    if (tid < MT) {
        int k = *topk_ptr;
        if (k < 1) k = 1;
        if (k > KMAX) k = KMAX;

        const int row = t0 + tid;
        float p[NE];
        float m = -3.402823466e+38f;
#pragma unroll
        for (int c = 0; c < NE; c++) { p[c] = L[tid * 65 + c]; m = fmaxf(m, p[c]); }
        float s = 0.f;
#pragma unroll
        for (int c = 0; c < NE; c++) { p[c] = __expf(p[c] - m); s += p[c]; }
        const float inv = 1.0f / s;
#pragma unroll
        for (int c = 0; c < NE; c++) p[c] *= inv;

        float* out_tp = out;
        float* out_ti = out + (size_t)N * k;
        float* out_pr = out + (size_t)2 * N * k;

        float* pr = out_pr + (size_t)row * NE;
#pragma unroll
        for (int c = 0; c < NE; c += 4)
            *(float4*)(pr + c) = make_float4(p[c], p[c + 1], p[c + 2], p[c + 3]);

        float tv[KMAX]; int ti[KMAX]; float ts = 0.f;
        for (int t = 0; t < KMAX; t++) {
            if (t >= k) break;
            float bv = -1.f; int bi = 0;
#pragma unroll
            for (int c = 0; c < NE; c++)
                if (p[c] > bv) { bv = p[c]; bi = c; }   // strict >: lowest-index ties
            tv[t] = bv; ti[t] = bi; ts += bv; p[bi] = -1.f;
        }
        const float tinv = 1.0f / ts;
        for (int t = 0; t < k; t++) {
            out_tp[(size_t)row * k + t] = tv[t] * tinv;
            out_ti[(size_t)row * k + t] = (float)ti[t];
        }
    }
}

extern "C" void kernel_launch(void* const* d_in, const int* in_sizes, int n_in,
                              void* d_out, int out_size) {
    const float* x    = (const float*)d_in[0];
    const float* w    = (const float*)d_in[1];
    const int*   topk = (const int*)d_in[2];
    float* out = (float*)d_out;

    const double s0 = (double)in_sizes[0];   // N*D
    const double s1 = (double)in_sizes[1];   // E*D
    const int kk = 2;                        // dataset k=2 (shape solve)
    const double r = s1 / s0;
    double Nd = (-2.0 * kk + sqrt(4.0 * kk * kk + 4.0 * r * (double)out_size)) / (2.0 * r);
    int N = (int)(Nd + 0.5);
    if (N <= 0) N = 16384;
    int D = (int)(s0 / N + 0.5);

    static int smem_set = 0;
    if (!smem_set) {
        cudaFuncSetAttribute(router_mma_kernel,
                             cudaFuncAttributeMaxDynamicSharedMemorySize, SMEM_TOTAL);
        smem_set = 1;
    }
    int grid = N / MT;
    router_mma_kernel<<<grid, 256, SMEM_TOTAL>>>(x, w, topk, out, N, D);
}

// round 6
// speedup vs baseline: 3.6119x; 1.1148x over previous
#include <cuda_runtime.h>
#include <cuda_bf16.h>
#include <cstdint>
#include <math.h>

#define NE    64     // experts
#define MT    128    // tokens per CTA
#define KB    64     // K per chunk (64 bf16 = 128B row, SW128 atom)
#define KMAX  8

// double-buffered smem: per-buffer 48KB
#define BUFSZ  49152
#define OFF_AH 0          // [128][128B] bf16 hi
#define OFF_AL 16384      // [128][128B] bf16 lo
#define OFF_BH 32768      // [64][128B]
#define OFF_BL 40960      // [64][128B]
#define SMEM_TOTAL (2 * BUFSZ)   // 96 KB

__device__ __forceinline__ uint32_t sw128(uint32_t off) {
    return off ^ ((off >> 3) & 0x70);
}

// fp32 pair -> bf16x2 hi + bf16x2 lo residual
__device__ __forceinline__ void cvt_hilo(float x, float y, uint32_t& h, uint32_t& l) {
    asm("cvt.rn.bf16x2.f32 %0, %1, %2;" : "=r"(h) : "f"(y), "f"(x));
    float hx = __uint_as_float(h << 16);
    float hy = __uint_as_float(h & 0xffff0000u);
    float lx = x - hx, ly = y - hy;
    asm("cvt.rn.bf16x2.f32 %0, %1, %2;" : "=r"(l) : "f"(ly), "f"(lx));
}

__device__ __forceinline__ void mma_bf16(float* c, const uint32_t* a, const uint32_t* b) {
    asm volatile(
        "mma.sync.aligned.m16n8k16.row.col.f32.bf16.bf16.f32 "
        "{%0,%1,%2,%3}, {%4,%5,%6,%7}, {%8,%9}, {%0,%1,%2,%3};"
        : "+f"(c[0]), "+f"(c[1]), "+f"(c[2]), "+f"(c[3])
        : "r"(a[0]), "r"(a[1]), "r"(a[2]), "r"(a[3]), "r"(b[0]), "r"(b[1]));
}

__device__ __forceinline__ void ldsm_x4(uint32_t& r0, uint32_t& r1, uint32_t& r2,
                                        uint32_t& r3, uint32_t addr) {
    asm volatile("ldmatrix.sync.aligned.m8n8.x4.shared.b16 {%0,%1,%2,%3}, [%4];"
                 : "=r"(r0), "=r"(r1), "=r"(r2), "=r"(r3) : "r"(addr));
}

__device__ __forceinline__ uint32_t smem_u32(const void* p) {
    uint32_t a;
    asm("{ .reg .u64 t; cvta.to.shared.u64 t, %1; cvt.u32.u64 %0, t; }" : "=r"(a) : "l"(p));
    return a;
}

extern __shared__ __align__(1024) unsigned char smem[];

__global__ __launch_bounds__(256, 1)
void router_mma_kernel(const float* __restrict__ x,
                       const float* __restrict__ w,
                       const int*   __restrict__ topk_ptr,
                       float* __restrict__ out,
                       int N, int D)
{
    const int tid  = threadIdx.x;
    const int wid  = tid >> 5;
    const int lane = tid & 31;
    const int t0   = blockIdx.x * MT;
    const uint32_t sb = smem_u32(smem);

    // 8 warps: 4 m-groups x 2 n-groups; warp tile = 32 rows x 32 cols
    const int Rb = (wid >> 1) * 32;
    const int Cb = (wid & 1) * 32;

    const int l4  = lane >> 2;           // 0..7
    const int lkp = lane & 3;            // 0..3
    const int mi  = lane >> 3;           // ldmatrix matrix index 0..3
    const int rL  = lane & 7;            // ldmatrix row-in-matrix

    // ldmatrix per-lane byte offsets (before swizzle), relative to tile base:
    // A (mt): matrices (m0,k0),(m8,k0),(m0,k8),(m8,k8)
    const uint32_t arow = (uint32_t)(Rb + (mi & 1) * 8 + rL);
    const uint32_t acol = (uint32_t)((mi >> 1) * 16);
    // B (nt pair): matrices (n0,k0),(n0,k8),(n8,k0),(n8,k8)
    const uint32_t brow = (uint32_t)(Cb + (mi >> 1) * 8 + rL);
    const uint32_t bcol = (uint32_t)((mi & 1) * 16);

    float acc[2][4][4];
#pragma unroll
    for (int mt = 0; mt < 2; mt++)
#pragma unroll
        for (int nt = 0; nt < 4; nt++)
#pragma unroll
            for (int i = 0; i < 4; i++) acc[mt][nt][i] = 0.f;

    float4 Areg[8], Breg[4];
    const int NC = D / KB;               // 32 chunks

    // prologue: prefetch chunk 0
#pragma unroll
    for (int q = 0; q < 8; q++) {
        int id = tid + q * 256, r = id >> 4, c4 = id & 15;
        Areg[q] = *(const float4*)(x + (size_t)(t0 + r) * D + c4 * 4);
    }
#pragma unroll
    for (int q = 0; q < 4; q++) {
        int id = tid + q * 256, r = id >> 4, c4 = id & 15;
        Breg[q] = *(const float4*)(w + (size_t)r * D + c4 * 4);
    }

    for (int kc = 0; kc < NC; kc++) {
        const uint32_t bufo = (uint32_t)((kc & 1) * BUFSZ);

        // ---- convert + store tiles (hi/lo bf16, SW128) ----
#pragma unroll
        for (int q = 0; q < 8; q++) {
            int id = tid + q * 256, r = id >> 4, c4 = id & 15;
            uint32_t h0, l0, h1, l1;
            cvt_hilo(Areg[q].x, Areg[q].y, h0, l0);
            cvt_hilo(Areg[q].z, Areg[q].w, h1, l1);
            uint32_t sw = sw128((uint32_t)(r * 128 + c4 * 8));
            *(uint2*)(smem + bufo + OFF_AH + sw) = make_uint2(h0, h1);
            *(uint2*)(smem + bufo + OFF_AL + sw) = make_uint2(l0, l1);
        }
#pragma unroll
        for (int q = 0; q < 4; q++) {
            int id = tid + q * 256, r = id >> 4, c4 = id & 15;
            uint32_t h0, l0, h1, l1;
            cvt_hilo(Breg[q].x, Breg[q].y, h0, l0);
            cvt_hilo(Breg[q].z, Breg[q].w, h1, l1);
            uint32_t sw = sw128((uint32_t)(r * 128 + c4 * 8));
            *(uint2*)(smem + bufo + OFF_BH + sw) = make_uint2(h0, h1);
            *(uint2*)(smem + bufo + OFF_BL + sw) = make_uint2(l0, l1);
        }

        // ---- prefetch next chunk (issued before barrier; consumed next iter) ----
        if (kc + 1 < NC) {
            const int k0 = (kc + 1) * KB;
#pragma unroll
            for (int q = 0; q < 8; q++) {
                int id = tid + q * 256, r = id >> 4, c4 = id & 15;
                Areg[q] = *(const float4*)(x + (size_t)(t0 + r) * D + k0 + c4 * 4);
            }
#pragma unroll
            for (int q = 0; q < 4; q++) {
                int id = tid + q * 256, r = id >> 4, c4 = id & 15;
                Breg[q] = *(const float4*)(w + (size_t)r * D + k0 + c4 * 4);
            }
        }

        __syncthreads();   // single barrier per chunk (double buffer)

        const uint32_t abase = sb + bufo + OFF_AH;
        const uint32_t albase = sb + bufo + OFF_AL;
        const uint32_t bbase = sb + bufo + OFF_BH;
        const uint32_t blbase = sb + bufo + OFF_BL;

        // ---- compute: 4 k16 steps, fragments via ldmatrix.x4 ----
#pragma unroll
        for (int ks = 0; ks < 4; ks++) {
            uint32_t bh[4][2], bl[4][2];
#pragma unroll
            for (int ntp = 0; ntp < 2; ntp++) {
                uint32_t boff = sw128((brow + ntp * 16) * 128 + (uint32_t)(ks * 32) + bcol);
                ldsm_x4(bh[ntp * 2][0], bh[ntp * 2][1], bh[ntp * 2 + 1][0], bh[ntp * 2 + 1][1],
                        bbase + boff);
                ldsm_x4(bl[ntp * 2][0], bl[ntp * 2][1], bl[ntp * 2 + 1][0], bl[ntp * 2 + 1][1],
                        blbase + boff);
            }
#pragma unroll
            for (int mt = 0; mt < 2; mt++) {
                uint32_t aoff = sw128((arow + mt * 16) * 128 + (uint32_t)(ks * 32) + acol);
                uint32_t ah[4], al[4];
                ldsm_x4(ah[0], ah[1], ah[2], ah[3], abase + aoff);
                ldsm_x4(al[0], al[1], al[2], al[3], albase + aoff);
#pragma unroll
                for (int nt = 0; nt < 4; nt++) {
                    mma_bf16(acc[mt][nt], ah, bh[nt]);
                    mma_bf16(acc[mt][nt], ah, bl[nt]);
                    mma_bf16(acc[mt][nt], al, bh[nt]);
                }
            }
        }
    }

    // ---- dump logits to L[128][65] (aliases buffer 0; last compute used buffer 1) ----
    float* L = (float*)smem;
#pragma unroll
    for (int mt = 0; mt < 2; mt++)
#pragma unroll
        for (int nt = 0; nt < 4; nt++) {
            int r0 = Rb + mt * 16 + l4;
            int c0 = Cb + nt * 8 + lkp * 2;
            L[r0 * 65 + c0]           = acc[mt][nt][0];
            L[r0 * 65 + c0 + 1]       = acc[mt][nt][1];
            L[(r0 + 8) * 65 + c0]     = acc[mt][nt][2];
            L[(r0 + 8) * 65 + c0 + 1] = acc[mt][nt][3];
        }
    __syncthreads();

    // ---- epilogue: one thread per row, thread-local softmax + top-k ----
    if (tid < MT) {
        int k = *topk_ptr;
        if (k < 1) k = 1;
        if (k > KMAX) k = KMAX;

        const int row = t0 + tid;
        float p[NE];
        float m = -3.402823466e+38f;
#pragma unroll
        for (int c = 0; c < NE; c++) { p[c] = L[tid * 65 + c]; m = fmaxf(m, p[c]); }
        float s = 0.f;
#pragma unroll
        for (int c = 0; c < NE; c++) { p[c] = __expf(p[c] - m); s += p[c]; }
        const float inv = 1.0f / s;
#pragma unroll
        for (int c = 0; c < NE; c++) p[c] *= inv;

        float* out_tp = out;
        float* out_ti = out + (size_t)N * k;
        float* out_pr = out + (size_t)2 * N * k;

        float* pr = out_pr + (size_t)row * NE;
#pragma unroll
        for (int c = 0; c < NE; c += 4)
            *(float4*)(pr + c) = make_float4(p[c], p[c + 1], p[c + 2], p[c + 3]);

        float tv[KMAX]; int ti[KMAX]; float ts = 0.f;
        for (int t = 0; t < KMAX; t++) {
            if (t >= k) break;
            float bv = -1.f; int bi = 0;
#pragma unroll
            for (int c = 0; c < NE; c++)
                if (p[c] > bv) { bv = p[c]; bi = c; }   // strict >: lowest-index ties
            tv[t] = bv; ti[t] = bi; ts += bv; p[bi] = -1.f;
        }
        const float tinv = 1.0f / ts;
        for (int t = 0; t < k; t++) {
            out_tp[(size_t)row * k + t] = tv[t] * tinv;
            out_ti[(size_t)row * k + t] = (float)ti[t];
        }
    }
}

extern "C" void kernel_launch(void* const* d_in, const int* in_sizes, int n_in,
                              void* d_out, int out_size) {
    const float* x    = (const float*)d_in[0];
    const float* w    = (const float*)d_in[1];
    const int*   topk = (const int*)d_in[2];
    float* out = (float*)d_out;

    const double s0 = (double)in_sizes[0];   // N*D
    const double s1 = (double)in_sizes[1];   // E*D
    const int kk = 2;                        // dataset k=2 (shape solve)
    const double r = s1 / s0;
    double Nd = (-2.0 * kk + sqrt(4.0 * kk * kk + 4.0 * r * (double)out_size)) / (2.0 * r);
    int N = (int)(Nd + 0.5);
    if (N <= 0) N = 16384;
    int D = (int)(s0 / N + 0.5);

    static int smem_set = 0;
    if (!smem_set) {
        cudaFuncSetAttribute(router_mma_kernel,
                             cudaFuncAttributeMaxDynamicSharedMemorySize, SMEM_TOTAL);
        smem_set = 1;
    }
    int grid = N / MT;
    router_mma_kernel<<<grid, 256, SMEM_TOTAL>>>(x, w, topk, out, N, D);
}